// round 5
// baseline (speedup 1.0000x reference)
#include <cuda_runtime.h>
#include <cstdint>

#define B_    8
#define L_    768
#define H_    16
#define DK_   64
#define D_    1024
#define BH_   128
#define M_    6144
#define SCALE 0.125f

// Scratch (device globals; allocation forbidden)
__device__ float g_Qp[BH_ * L_ * DK_];                 // [bh][l][dk] (tf32-rounded)
__device__ float g_Kp[BH_ * L_ * DK_];                 // (tf32-rounded)
__device__ float g_Vt[BH_ * DK_ * L_];                 // V^T [bh][dk][l] (tf32-rounded)
__device__ float g_Ec[1535 * 64];                      // tf32-rounded rel embedding
__device__ float g_S [(size_t)BH_ * L_ * L_];          // raw content scores
__device__ float g_Rw[(size_t)BH_ * 6 * 128 * 896];    // raw rel windows
__device__ float g_O2[(size_t)M_ * D_];                // attn out, merged

__device__ __forceinline__ float to_tf32(float x) {
    float r;
    asm("cvt.rna.tf32.f32 %0, %1;" : "=f"(r) : "f"(x));
    return r;
}
__device__ __forceinline__ uint32_t smem_u32(const void* p) {
    uint32_t a;
    asm("{ .reg .u64 t; cvta.to.shared.u64 t, %1; cvt.u32.u64 %0, t; }"
        : "=r"(a) : "l"(p));
    return a;
}
__device__ __forceinline__ void mma_tf32(float* d, const uint32_t* a, const uint32_t* b) {
    asm volatile(
        "mma.sync.aligned.m16n8k8.row.col.f32.tf32.tf32.f32 "
        "{%0,%1,%2,%3}, {%4,%5,%6,%7}, {%8,%9}, {%0,%1,%2,%3};"
        : "+f"(d[0]), "+f"(d[1]), "+f"(d[2]), "+f"(d[3])
        : "r"(a[0]), "r"(a[1]), "r"(a[2]), "r"(a[3]), "r"(b[0]), "r"(b[1]));
}
#define CP_A16(dst, src) \
    asm volatile("cp.async.ca.shared.global [%0], [%1], 16;" :: "r"(dst), "l"(src) : "memory")
#define CP_A16Z(dst, src, sz) \
    asm volatile("cp.async.ca.shared.global [%0], [%1], 16, %2;" :: "r"(dst), "l"(src), "r"(sz) : "memory")
#define CP_COMMIT() asm volatile("cp.async.commit_group;" ::: "memory")
#define CP_WAIT(N)  asm volatile("cp.async.wait_group %0;" :: "n"(N) : "memory")

// ---------------------------------------------------------------------------
// Warp-MMA tf32 GEMM (projections): C[128,128] = A[128,K] @ B[128,K]^T
// MODE 0: Q/K projection (OUT head-split, tf32-rounded)
// MODE 1: V projection   (writes g_Vt transposed, tf32-rounded)
// MODE 4: out projection (plain fp32 OUT)
// ---------------------------------------------------------------------------
template<int MODE>
__global__ __launch_bounds__(256)
void mma_gemm(const float* __restrict__ Ag, const float* __restrict__ Bg,
              const float* __restrict__ bias, float* __restrict__ OUT)
{
    constexpr int NT = 1024 / 8;

    __shared__ float As[2][8][136];
    __shared__ float Bs[2][8][136];

    const int tid  = threadIdx.x;
    const int wid  = tid >> 5;
    const int lane = tid & 31;
    const int wm   = (wid & 1) * 64;
    const int wn   = (wid >> 1) * 32;
    const int g4   = lane >> 2;
    const int cq   = lane & 3;

    const float* Arow = Ag + (size_t)(blockIdx.y * 128) * 1024;
    const float* Brow = Bg + (size_t)(blockIdx.x * 128) * 1024;

    const int lr = tid >> 1, lseg = (tid & 1) * 4;

    auto load_tile = [&](int t, int buf) {
        const int k0 = t * 8;
        float4 va = *(const float4*)(Arow + (size_t)lr * 1024 + k0 + lseg);
        As[buf][lseg + 0][lr] = to_tf32(va.x);
        As[buf][lseg + 1][lr] = to_tf32(va.y);
        As[buf][lseg + 2][lr] = to_tf32(va.z);
        As[buf][lseg + 3][lr] = to_tf32(va.w);
        float4 vb = *(const float4*)(Brow + (size_t)lr * 1024 + k0 + lseg);
        Bs[buf][lseg + 0][lr] = to_tf32(vb.x);
        Bs[buf][lseg + 1][lr] = to_tf32(vb.y);
        Bs[buf][lseg + 2][lr] = to_tf32(vb.z);
        Bs[buf][lseg + 3][lr] = to_tf32(vb.w);
    };

    float acc[4][4][4];
#pragma unroll
    for (int i = 0; i < 4; ++i)
#pragma unroll
        for (int j = 0; j < 4; ++j)
#pragma unroll
            for (int k = 0; k < 4; ++k) acc[i][j][k] = 0.f;

    load_tile(0, 0);
    __syncthreads();

    for (int t = 0; t < NT; ++t) {
        const int buf = t & 1;
        float4 pa, pb;
        const bool nx = (t + 1 < NT);
        if (nx) {
            const int k1 = (t + 1) * 8;
            pa = *(const float4*)(Arow + (size_t)lr * 1024 + k1 + lseg);
            pb = *(const float4*)(Brow + (size_t)lr * 1024 + k1 + lseg);
        }
        uint32_t afr[4][4], bfr[4][2];
#pragma unroll
        for (int m = 0; m < 4; ++m) {
            const int m0 = wm + m * 16;
            afr[m][0] = __float_as_uint(As[buf][cq    ][m0 + g4    ]);
            afr[m][1] = __float_as_uint(As[buf][cq    ][m0 + g4 + 8]);
            afr[m][2] = __float_as_uint(As[buf][cq + 4][m0 + g4    ]);
            afr[m][3] = __float_as_uint(As[buf][cq + 4][m0 + g4 + 8]);
        }
#pragma unroll
        for (int n = 0; n < 4; ++n) {
            const int n0 = wn + n * 8;
            bfr[n][0] = __float_as_uint(Bs[buf][cq    ][n0 + g4]);
            bfr[n][1] = __float_as_uint(Bs[buf][cq + 4][n0 + g4]);
        }
#pragma unroll
        for (int m = 0; m < 4; ++m)
#pragma unroll
            for (int n = 0; n < 4; ++n)
                mma_tf32(acc[m][n], afr[m], bfr[n]);

        if (nx) {
            const int nb = buf ^ 1;
            As[nb][lseg + 0][lr] = to_tf32(pa.x);
            As[nb][lseg + 1][lr] = to_tf32(pa.y);
            As[nb][lseg + 2][lr] = to_tf32(pa.z);
            As[nb][lseg + 3][lr] = to_tf32(pa.w);
            Bs[nb][lseg + 0][lr] = to_tf32(pb.x);
            Bs[nb][lseg + 1][lr] = to_tf32(pb.y);
            Bs[nb][lseg + 2][lr] = to_tf32(pb.z);
            Bs[nb][lseg + 3][lr] = to_tf32(pb.w);
        }
        __syncthreads();
    }

#pragma unroll
    for (int m = 0; m < 4; ++m) {
#pragma unroll
        for (int n = 0; n < 4; ++n) {
            const int col = wn + n * 8 + cq * 2;
#pragma unroll
            for (int h2 = 0; h2 < 2; ++h2) {
                const int row = wm + m * 16 + g4 + h2 * 8;
                const float c0 = acc[m][n][h2 * 2 + 0];
                const float c1 = acc[m][n][h2 * 2 + 1];
                const int mg = blockIdx.y * 128 + row;
                const int ng = blockIdx.x * 128 + col;
                if constexpr (MODE == 0) {
                    const int bb = mg / 768, l = mg - bb * 768;
                    const int hh = ng >> 6, dd = ng & 63;
                    float* dst = OUT + (((size_t)(bb * 16 + hh) * 768) + l) * 64 + dd;
                    dst[0] = to_tf32(c0 + bias[ng]);
                    dst[1] = to_tf32(c1 + bias[ng + 1]);
                } else if constexpr (MODE == 1) {
                    const int bb = mg / 768, l = mg - bb * 768;
                    const int hh = ng >> 6, dd = ng & 63;
                    g_Vt[((size_t)(bb * 16 + hh) * 64 + dd    ) * 768 + l] = to_tf32(c0 + bias[ng]);
                    g_Vt[((size_t)(bb * 16 + hh) * 64 + dd + 1) * 768 + l] = to_tf32(c1 + bias[ng + 1]);
                } else {
                    float* dst = OUT + (size_t)mg * 1024 + ng;
                    dst[0] = c0 + bias[ng];
                    dst[1] = c1 + bias[ng + 1];
                }
            }
        }
    }
}

// ---------------------------------------------------------------------------
// E pre-round kernel: g_Ec = tf32(relE)
// ---------------------------------------------------------------------------
__global__ __launch_bounds__(256)
void conv_e(const float* __restrict__ E)
{
    int i = blockIdx.x * 256 + threadIdx.x;
    if (i < 1535 * 64) g_Ec[i] = to_tf32(E[i]);
}

// ---------------------------------------------------------------------------
// Scores: one CTA per (qt, bh). A-frags (Q) persist in registers across K=64;
// loops all 13 xt tiles (6 content K-tiles + 7 rel E-window tiles) with
// cp.async double-buffered B. Writes raw scores to g_S / g_Rw.
// 8 warps as 4m x 2n; warp tile 32 x 64.
// ---------------------------------------------------------------------------
__global__ __launch_bounds__(256)
void scores_kernel()
{
    extern __shared__ float sm[];
    float* Qs = sm;                       // [128][68]
    float* Bs = sm + 128 * 68;            // [2][128][68]
    const uint32_t qs_a = smem_u32(Qs);
    const uint32_t bs_a = smem_u32(Bs);

    const int tid  = threadIdx.x;
    const int lane = tid & 31, wid = tid >> 5;
    const int g4 = lane >> 2, cq = lane & 3;
    const int wm = (wid & 3) * 32, wn = (wid >> 2) * 64;
    const int qt = blockIdx.x, bh = blockIdx.y;

    const float* Qg = g_Qp + ((size_t)bh * 768 + qt * 128) * 64;
    const float* Kg = g_Kp + (size_t)bh * 768 * 64;

    // stage Q (tf32-valued already): 128x64
#pragma unroll
    for (int i = 0; i < 8; ++i) {
        int idx = tid + i * 256;
        int r = idx >> 4, seg = idx & 15;
        CP_A16(qs_a + (r * 68 + seg * 4) * 4, Qg + r * 64 + seg * 4);
    }

    auto copyB = [&](int xt) {
        const uint32_t base = bs_a + (uint32_t)(xt & 1) * (128 * 68 * 4);
        if (xt < 6) {
            const float* s0 = Kg + (size_t)xt * 128 * 64;
#pragma unroll
            for (int i = 0; i < 8; ++i) {
                int idx = tid + i * 256;
                int r = idx >> 4, seg = idx & 15;
                CP_A16(base + (r * 68 + seg * 4) * 4, s0 + r * 64 + seg * 4);
            }
        } else {
            const int jbase = 640 - 128 * qt + (xt - 6) * 128;
#pragma unroll
            for (int i = 0; i < 8; ++i) {
                int idx = tid + i * 256;
                int r = idx >> 4, seg = idx & 15;
                int j = jbase + r;
                int jc = (j > 1534) ? 1534 : j;
                unsigned sz = (j <= 1534) ? 16u : 0u;
                CP_A16Z(base + (r * 68 + seg * 4) * 4, g_Ec + (size_t)jc * 64 + seg * 4, sz);
            }
        }
    };

    copyB(0); CP_COMMIT();     // G0 = Q + B0
    copyB(1); CP_COMMIT();     // G1 = B1
    CP_WAIT(1);
    __syncthreads();

    // persistent A fragments: [kstep][mtile][4]
    uint32_t afr[8][2][4];
#pragma unroll
    for (int ks = 0; ks < 8; ++ks)
#pragma unroll
        for (int mt = 0; mt < 2; ++mt) {
            const float* q = Qs + (wm + mt * 16 + g4) * 68 + ks * 8 + cq;
            afr[ks][mt][0] = __float_as_uint(q[0]);
            afr[ks][mt][1] = __float_as_uint(q[8 * 68]);
            afr[ks][mt][2] = __float_as_uint(q[4]);
            afr[ks][mt][3] = __float_as_uint(q[8 * 68 + 4]);
        }

#pragma unroll 1
    for (int xt = 0; xt < 13; ++xt) {
        const float* Bsb = Bs + (xt & 1) * (128 * 68);
        float acc[2][8][4] = {};

#pragma unroll
        for (int ks = 0; ks < 8; ++ks) {
            uint32_t bfr[8][2];
#pragma unroll
            for (int nt = 0; nt < 8; ++nt) {
                const float* b = Bsb + (wn + nt * 8 + g4) * 68 + ks * 8 + cq;
                bfr[nt][0] = __float_as_uint(b[0]);
                bfr[nt][1] = __float_as_uint(b[4]);
            }
#pragma unroll
            for (int mt = 0; mt < 2; ++mt)
#pragma unroll
                for (int nt = 0; nt < 8; ++nt)
                    mma_tf32(acc[mt][nt], afr[ks][mt], bfr[nt]);
        }

        // epilogue (raw scores)
#pragma unroll
        for (int mt = 0; mt < 2; ++mt)
#pragma unroll
            for (int h2 = 0; h2 < 2; ++h2) {
                const int row = wm + mt * 16 + g4 + h2 * 8;
#pragma unroll
                for (int nt = 0; nt < 8; ++nt) {
                    const int col = wn + nt * 8 + 2 * cq;
                    float2 v = make_float2(acc[mt][nt][h2 * 2 + 0],
                                           acc[mt][nt][h2 * 2 + 1]);
                    if (xt < 6)
                        *(float2*)&g_S[((size_t)bh * 768 + qt * 128 + row) * 768
                                       + xt * 128 + col] = v;
                    else
                        *(float2*)&g_Rw[(((size_t)bh * 6 + qt) * 128 + row) * 896
                                        + (xt - 6) * 128 + col] = v;
                }
            }

        __syncthreads();
        if (xt + 2 < 13) { copyB(xt + 2); CP_COMMIT(); }
        if (xt + 1 < 13) {
            if (xt + 2 < 13) { CP_WAIT(1); } else { CP_WAIT(0); }
            __syncthreads();
        }
    }
}

// ---------------------------------------------------------------------------
// Fused rel+softmax+AV: one CTA per (qt, bh). For each k-tile: load raw S and
// Rw in A-frag layout, p = exp(SCALE*(s+r)) (no max; scores are O(1)), feed
// PV MMA with V (tf32, cp.async double-buffered), accumulate row sums,
// normalize at the end. 8 warps; warp tile 16q x 64d.
// ---------------------------------------------------------------------------
__global__ __launch_bounds__(256)
void av_fused()
{
    extern __shared__ float sm[];         // Vs[2][64][132]
    const uint32_t vs_a = smem_u32(sm);

    const int tid  = threadIdx.x;
    const int lane = tid & 31, wid = tid >> 5;
    const int g4 = lane >> 2, cq = lane & 3;
    const int qt = blockIdx.x, bh = blockIdx.y;
    const int rlo = wid * 16 + g4, rhi = rlo + 8;

    const float* Sb  = g_S + ((size_t)bh * 768 + qt * 128) * 768;
    const float* SLo = Sb + (size_t)rlo * 768;
    const float* SHi = Sb + (size_t)rhi * 768;
    const float* RwLo = g_Rw + (((size_t)bh * 6 + qt) * 128 + rlo) * 896 + (127 - rlo);
    const float* RwHi = g_Rw + (((size_t)bh * 6 + qt) * 128 + rhi) * 896 + (127 - rhi);
    const float* Vg = g_Vt + (size_t)bh * 64 * 768;

    auto copyV = [&](int kt) {
        const uint32_t base = vs_a + (uint32_t)(kt & 1) * (64 * 132 * 4);
#pragma unroll
        for (int i = 0; i < 8; ++i) {
            int idx = tid + i * 256;         // 2048 float4 = 64 rows x 32 segs
            int d = idx >> 5, seg = idx & 31;
            CP_A16(base + (d * 132 + seg * 4) * 4,
                   Vg + (size_t)d * 768 + kt * 128 + seg * 4);
        }
    };

    copyV(0); CP_COMMIT();
    copyV(1); CP_COMMIT();
    CP_WAIT(1);
    __syncthreads();

    float acc[8][4] = {};
    float l0 = 0.f, l1 = 0.f;

#pragma unroll 1
    for (int kt = 0; kt < 6; ++kt) {
        const float* Vsb = sm + (kt & 1) * (64 * 132);
#pragma unroll 4
        for (int ks = 0; ks < 16; ++ks) {
            const int kc = kt * 128 + ks * 8 + cq;
            float s0 = SLo[kc], s2 = SLo[kc + 4];
            float s1 = SHi[kc], s3 = SHi[kc + 4];
            float r0 = RwLo[kc], r2 = RwLo[kc + 4];
            float r1 = RwHi[kc], r3 = RwHi[kc + 4];
            float p0 = __expf(SCALE * (s0 + r0));
            float p1 = __expf(SCALE * (s1 + r1));
            float p2 = __expf(SCALE * (s2 + r2));
            float p3 = __expf(SCALE * (s3 + r3));
            l0 += p0 + p2;
            l1 += p1 + p3;
            uint32_t a[4] = { __float_as_uint(to_tf32(p0)),
                              __float_as_uint(to_tf32(p1)),
                              __float_as_uint(to_tf32(p2)),
                              __float_as_uint(to_tf32(p3)) };
#pragma unroll
            for (int nt = 0; nt < 8; ++nt) {
                const float* b = Vsb + (nt * 8 + g4) * 132 + ks * 8 + cq;
                uint32_t bf[2] = { __float_as_uint(b[0]), __float_as_uint(b[4]) };
                mma_tf32(acc[nt], a, bf);
            }
        }
        __syncthreads();
        if (kt + 2 < 6) { copyV(kt + 2); CP_COMMIT(); }
        if (kt + 1 < 6) {
            if (kt + 2 < 6) { CP_WAIT(1); } else { CP_WAIT(0); }
            __syncthreads();
        }
    }

    // row sums (quad reduce) and normalize
    l0 += __shfl_xor_sync(0xffffffffu, l0, 1);
    l0 += __shfl_xor_sync(0xffffffffu, l0, 2);
    l1 += __shfl_xor_sync(0xffffffffu, l1, 1);
    l1 += __shfl_xor_sync(0xffffffffu, l1, 2);
    const float i0 = 1.f / l0, i1 = 1.f / l1;

    const int b = bh >> 4, h = bh & 15;
#pragma unroll
    for (int nt = 0; nt < 8; ++nt) {
        const int col = h * 64 + nt * 8 + 2 * cq;
        *(float2*)&g_O2[((size_t)(b * 768) + qt * 128 + rlo) * 1024 + col] =
            make_float2(acc[nt][0] * i0, acc[nt][1] * i0);
        *(float2*)&g_O2[((size_t)(b * 768) + qt * 128 + rhi) * 1024 + col] =
            make_float2(acc[nt][2] * i1, acc[nt][3] * i1);
    }
}

// ---------------------------------------------------------------------------
extern "C" void kernel_launch(void* const* d_in, const int* in_sizes, int n_in,
                              void* d_out, int out_size)
{
    const float* query = (const float*)d_in[0];
    const float* key   = (const float*)d_in[1];
    const float* value = (const float*)d_in[2];
    const float* w_q   = (const float*)d_in[3];
    const float* b_q   = (const float*)d_in[4];
    const float* w_k   = (const float*)d_in[5];
    const float* b_k   = (const float*)d_in[6];
    const float* w_v   = (const float*)d_in[7];
    const float* b_v   = (const float*)d_in[8];
    const float* w_o   = (const float*)d_in[9];
    const float* b_o   = (const float*)d_in[10];
    const float* relE  = (const float*)d_in[11];
    float* out = (float*)d_out;

    float *qp, *kp, *o2;
    cudaGetSymbolAddress((void**)&qp, g_Qp);
    cudaGetSymbolAddress((void**)&kp, g_Kp);
    cudaGetSymbolAddress((void**)&o2, g_O2);

    const int SC_SMEM = 3 * 128 * 68 * 4;   // 104448
    const int AV_SMEM = 2 * 64 * 132 * 4;   //  67584
    cudaFuncSetAttribute(scores_kernel, cudaFuncAttributeMaxDynamicSharedMemorySize, SC_SMEM);
    cudaFuncSetAttribute(av_fused,      cudaFuncAttributeMaxDynamicSharedMemorySize, AV_SMEM);

    mma_gemm<0><<<dim3(8, 48), 256>>>(query, w_q, b_q, qp);
    mma_gemm<0><<<dim3(8, 48), 256>>>(key,   w_k, b_k, kp);
    mma_gemm<1><<<dim3(8, 48), 256>>>(value, w_v, b_v, nullptr);

    conv_e<<<384, 256>>>(relE);

    scores_kernel<<<dim3(6, 128), 256, SC_SMEM>>>();

    av_fused<<<dim3(6, 128), 256, AV_SMEM>>>();

    mma_gemm<4><<<dim3(8, 48), 256>>>(o2, w_o, b_o, out);
}

// round 6
// speedup vs baseline: 1.5245x; 1.5245x over previous
#include <cuda_runtime.h>
#include <cstdint>

#define B_    8
#define L_    768
#define H_    16
#define DK_   64
#define D_    1024
#define BH_   128
#define M_    6144
#define SCALE 0.125f

// Scratch (device globals; allocation forbidden)
__device__ float g_Xr[M_ * D_];                        // tf32-rounded input X
__device__ float g_Wq[D_ * D_], g_Wk[D_ * D_], g_Wv[D_ * D_], g_Wo[D_ * D_];
__device__ float g_Qp[BH_ * L_ * DK_];                 // [bh][l][dk] tf32
__device__ float g_Kp[BH_ * L_ * DK_];                 // tf32
__device__ float g_Vt[BH_ * DK_ * L_];                 // V^T [bh][dk][l] tf32
__device__ float g_Ec[1535 * 64];                      // tf32 rel embedding
__device__ float g_S [(size_t)BH_ * L_ * L_];          // scores -> probs
__device__ float g_Rw[(size_t)BH_ * 6 * 128 * 896];    // rel windows
__device__ float g_O2[(size_t)M_ * D_];                // attn out, merged, tf32

__device__ __forceinline__ float to_tf32(float x) {
    float r;
    asm("cvt.rna.tf32.f32 %0, %1;" : "=f"(r) : "f"(x));
    return r;
}
__device__ __forceinline__ uint32_t smem_u32(const void* p) {
    uint32_t a;
    asm("{ .reg .u64 t; cvta.to.shared.u64 t, %1; cvt.u32.u64 %0, t; }"
        : "=r"(a) : "l"(p));
    return a;
}
__device__ __forceinline__ void mma_tf32(float* d, const uint32_t* a, const uint32_t* b) {
    asm volatile(
        "mma.sync.aligned.m16n8k8.row.col.f32.tf32.tf32.f32 "
        "{%0,%1,%2,%3}, {%4,%5,%6,%7}, {%8,%9}, {%0,%1,%2,%3};"
        : "+f"(d[0]), "+f"(d[1]), "+f"(d[2]), "+f"(d[3])
        : "r"(a[0]), "r"(a[1]), "r"(a[2]), "r"(a[3]), "r"(b[0]), "r"(b[1]));
}
#define CP_A16(dst, src) \
    asm volatile("cp.async.ca.shared.global [%0], [%1], 16;" :: "r"(dst), "l"(src) : "memory")
#define CP_A16Z(dst, src, sz) \
    asm volatile("cp.async.ca.shared.global [%0], [%1], 16, %2;" :: "r"(dst), "l"(src), "r"(sz) : "memory")
#define CP_COMMIT() asm volatile("cp.async.commit_group;" ::: "memory")
#define CP_WAIT1()  asm volatile("cp.async.wait_group 1;" ::: "memory")
#define CP_WAIT0()  asm volatile("cp.async.wait_group 0;" ::: "memory")

// ---------------------------------------------------------------------------
// tf32 pre-round: out[i] = tf32(in[i]), vectorized
// ---------------------------------------------------------------------------
__global__ __launch_bounds__(256)
void conv_tf32(const float4* __restrict__ in, float4* __restrict__ out, int n4)
{
    int i = blockIdx.x * 256 + threadIdx.x;
    if (i < n4) {
        float4 v = in[i];
        out[i] = make_float4(to_tf32(v.x), to_tf32(v.y), to_tf32(v.z), to_tf32(v.w));
    }
}

// ---------------------------------------------------------------------------
// Projection GEMM: C[128,128] = A[128,1024] @ B[128,1024]^T, operands already
// tf32-rounded in global. BK=32, 3-stage cp.async, smem stride 36 (bank-free).
// MODE 0: Q/K proj (head-split OUT, tf32-round)
// MODE 1: V proj   (g_Vt transposed, tf32-round)
// MODE 2: out proj (plain fp32 OUT)
// ---------------------------------------------------------------------------
template<int MODE>
__global__ __launch_bounds__(256)
void proj_mma(const float* __restrict__ Ag, const float* __restrict__ Bg,
              const float* __restrict__ bias, float* __restrict__ OUT)
{
    extern __shared__ float sm[];
    const uint32_t smb = smem_u32(sm);
    constexpr int STG = 2 * 128 * 36;      // floats per stage (A then B)

    const int tid = threadIdx.x, lane = tid & 31, wid = tid >> 5;
    const int g4 = lane >> 2, cq = lane & 3;
    const int wm = (wid & 1) * 64, wn = (wid >> 1) * 32;

    const float* Arow = Ag + (size_t)(blockIdx.y * 128) * 1024;
    const float* Brow = Bg + (size_t)(blockIdx.x * 128) * 1024;

    auto loadAB = [&](int t, int s) {
        const uint32_t base = smb + (uint32_t)s * STG * 4;
        const int k0 = t * 32;
#pragma unroll
        for (int i = 0; i < 4; ++i) {
            int idx = tid + i * 256;
            int r = idx >> 3, seg = idx & 7;
            CP_A16(base + (uint32_t)(r * 36 + seg * 4) * 4,
                   Arow + (size_t)r * 1024 + k0 + seg * 4);
        }
#pragma unroll
        for (int i = 0; i < 4; ++i) {
            int idx = tid + i * 256;
            int r = idx >> 3, seg = idx & 7;
            CP_A16(base + (uint32_t)(128 * 36 + r * 36 + seg * 4) * 4,
                   Brow + (size_t)r * 1024 + k0 + seg * 4);
        }
    };

    float acc[4][4][4] = {};

    loadAB(0, 0); CP_COMMIT();
    loadAB(1, 1); CP_COMMIT();

    for (int t = 0; t < 32; ++t) {
        if (t < 31) { CP_WAIT1(); } else { CP_WAIT0(); }
        __syncthreads();
        if (t + 2 < 32) { loadAB(t + 2, (t + 2) % 3); CP_COMMIT(); }

        const float* As = sm + (t % 3) * STG;
        const float* Bs = As + 128 * 36;
#pragma unroll
        for (int ks = 0; ks < 4; ++ks) {
            uint32_t afr[4][4], bfr[4][2];
#pragma unroll
            for (int m = 0; m < 4; ++m) {
                const float* p = As + (wm + m * 16 + g4) * 36 + ks * 8 + cq;
                afr[m][0] = __float_as_uint(p[0]);
                afr[m][1] = __float_as_uint(p[8 * 36]);
                afr[m][2] = __float_as_uint(p[4]);
                afr[m][3] = __float_as_uint(p[8 * 36 + 4]);
            }
#pragma unroll
            for (int n = 0; n < 4; ++n) {
                const float* p = Bs + (wn + n * 8 + g4) * 36 + ks * 8 + cq;
                bfr[n][0] = __float_as_uint(p[0]);
                bfr[n][1] = __float_as_uint(p[4]);
            }
#pragma unroll
            for (int m = 0; m < 4; ++m)
#pragma unroll
                for (int n = 0; n < 4; ++n)
                    mma_tf32(acc[m][n], afr[m], bfr[n]);
        }
    }

#pragma unroll
    for (int m = 0; m < 4; ++m) {
#pragma unroll
        for (int n = 0; n < 4; ++n) {
            const int col = wn + n * 8 + cq * 2;
#pragma unroll
            for (int h2 = 0; h2 < 2; ++h2) {
                const int row = wm + m * 16 + g4 + h2 * 8;
                const float c0 = acc[m][n][h2 * 2 + 0];
                const float c1 = acc[m][n][h2 * 2 + 1];
                const int mg = blockIdx.y * 128 + row;
                const int ng = blockIdx.x * 128 + col;
                if constexpr (MODE == 0) {
                    const int bb = mg / 768, l = mg - bb * 768;
                    const int hh = ng >> 6, dd = ng & 63;
                    float* dst = OUT + (((size_t)(bb * 16 + hh) * 768) + l) * 64 + dd;
                    dst[0] = to_tf32(c0 + bias[ng]);
                    dst[1] = to_tf32(c1 + bias[ng + 1]);
                } else if constexpr (MODE == 1) {
                    const int bb = mg / 768, l = mg - bb * 768;
                    const int hh = ng >> 6, dd = ng & 63;
                    g_Vt[((size_t)(bb * 16 + hh) * 64 + dd    ) * 768 + l] = to_tf32(c0 + bias[ng]);
                    g_Vt[((size_t)(bb * 16 + hh) * 64 + dd + 1) * 768 + l] = to_tf32(c1 + bias[ng + 1]);
                } else {
                    float* dst = OUT + (size_t)mg * 1024 + ng;
                    dst[0] = c0 + bias[ng];
                    dst[1] = c1 + bias[ng + 1];
                }
            }
        }
    }
}

// ---------------------------------------------------------------------------
// Scores (unchanged from R5): one CTA per (qt, bh); Q A-frags persistent;
// 13 xt tiles (6 content + 7 rel window), cp.async double-buffered B.
// ---------------------------------------------------------------------------
__global__ __launch_bounds__(256)
void scores_kernel()
{
    extern __shared__ float sm[];
    float* Qs = sm;                       // [128][68]
    float* Bs = sm + 128 * 68;            // [2][128][68]
    const uint32_t qs_a = smem_u32(Qs);
    const uint32_t bs_a = smem_u32(Bs);

    const int tid  = threadIdx.x;
    const int lane = tid & 31, wid = tid >> 5;
    const int g4 = lane >> 2, cq = lane & 3;
    const int wm = (wid & 3) * 32, wn = (wid >> 2) * 64;
    const int qt = blockIdx.x, bh = blockIdx.y;

    const float* Qg = g_Qp + ((size_t)bh * 768 + qt * 128) * 64;
    const float* Kg = g_Kp + (size_t)bh * 768 * 64;

#pragma unroll
    for (int i = 0; i < 8; ++i) {
        int idx = tid + i * 256;
        int r = idx >> 4, seg = idx & 15;
        CP_A16(qs_a + (r * 68 + seg * 4) * 4, Qg + r * 64 + seg * 4);
    }

    auto copyB = [&](int xt) {
        const uint32_t base = bs_a + (uint32_t)(xt & 1) * (128 * 68 * 4);
        if (xt < 6) {
            const float* s0 = Kg + (size_t)xt * 128 * 64;
#pragma unroll
            for (int i = 0; i < 8; ++i) {
                int idx = tid + i * 256;
                int r = idx >> 4, seg = idx & 15;
                CP_A16(base + (r * 68 + seg * 4) * 4, s0 + r * 64 + seg * 4);
            }
        } else {
            const int jbase = 640 - 128 * qt + (xt - 6) * 128;
#pragma unroll
            for (int i = 0; i < 8; ++i) {
                int idx = tid + i * 256;
                int r = idx >> 4, seg = idx & 15;
                int j = jbase + r;
                int jc = (j > 1534) ? 1534 : j;
                unsigned sz = (j <= 1534) ? 16u : 0u;
                CP_A16Z(base + (r * 68 + seg * 4) * 4, g_Ec + (size_t)jc * 64 + seg * 4, sz);
            }
        }
    };

    copyB(0); CP_COMMIT();
    copyB(1); CP_COMMIT();
    CP_WAIT1();
    __syncthreads();

    uint32_t afr[8][2][4];
#pragma unroll
    for (int ks = 0; ks < 8; ++ks)
#pragma unroll
        for (int mt = 0; mt < 2; ++mt) {
            const float* q = Qs + (wm + mt * 16 + g4) * 68 + ks * 8 + cq;
            afr[ks][mt][0] = __float_as_uint(q[0]);
            afr[ks][mt][1] = __float_as_uint(q[8 * 68]);
            afr[ks][mt][2] = __float_as_uint(q[4]);
            afr[ks][mt][3] = __float_as_uint(q[8 * 68 + 4]);
        }

#pragma unroll 1
    for (int xt = 0; xt < 13; ++xt) {
        const float* Bsb = Bs + (xt & 1) * (128 * 68);
        float acc[2][8][4] = {};

#pragma unroll
        for (int ks = 0; ks < 8; ++ks) {
            uint32_t bfr[8][2];
#pragma unroll
            for (int nt = 0; nt < 8; ++nt) {
                const float* b = Bsb + (wn + nt * 8 + g4) * 68 + ks * 8 + cq;
                bfr[nt][0] = __float_as_uint(b[0]);
                bfr[nt][1] = __float_as_uint(b[4]);
            }
#pragma unroll
            for (int mt = 0; mt < 2; ++mt)
#pragma unroll
                for (int nt = 0; nt < 8; ++nt)
                    mma_tf32(acc[mt][nt], afr[ks][mt], bfr[nt]);
        }

#pragma unroll
        for (int mt = 0; mt < 2; ++mt)
#pragma unroll
            for (int h2 = 0; h2 < 2; ++h2) {
                const int row = wm + mt * 16 + g4 + h2 * 8;
#pragma unroll
                for (int nt = 0; nt < 8; ++nt) {
                    const int col = wn + nt * 8 + 2 * cq;
                    float2 v = make_float2(acc[mt][nt][h2 * 2 + 0],
                                           acc[mt][nt][h2 * 2 + 1]);
                    if (xt < 6)
                        *(float2*)&g_S[((size_t)bh * 768 + qt * 128 + row) * 768
                                       + xt * 128 + col] = v;
                    else
                        *(float2*)&g_Rw[(((size_t)bh * 6 + qt) * 128 + row) * 896
                                        + (xt - 6) * 128 + col] = v;
                }
            }

        __syncthreads();
        if (xt + 2 < 13) { copyB(xt + 2); CP_COMMIT(); }
        if (xt + 1 < 13) {
            if (xt + 2 < 13) { CP_WAIT1(); } else { CP_WAIT0(); }
            __syncthreads();
        }
    }
}

// ---------------------------------------------------------------------------
// Fused rel-add + scale + softmax (R4-proven, coalesced). Writes tf32-rounded
// probabilities in place so av can cp.async raw.
// ---------------------------------------------------------------------------
__global__ __launch_bounds__(256)
void softmax_rel()
{
    const int row = blockIdx.x;
    const int bh  = row / 768;
    const int q   = row - bh * 768;
    const int qt  = q >> 7, qi = q & 127;

    float* s = g_S + (size_t)row * 768;
    const float* r = g_Rw + (((size_t)bh * 6 + qt) * 128 + qi) * 896 + (127 - qi);

    const int t = threadIdx.x;
    float v0 = SCALE * (s[t]       + r[t]);
    float v1 = SCALE * (s[t + 256] + r[t + 256]);
    float v2 = SCALE * (s[t + 512] + r[t + 512]);

    __shared__ float sred[8];
    __shared__ float sbcast;

    float m = fmaxf(v0, fmaxf(v1, v2));
#pragma unroll
    for (int o = 16; o; o >>= 1) m = fmaxf(m, __shfl_xor_sync(0xffffffffu, m, o));
    if ((t & 31) == 0) sred[t >> 5] = m;
    __syncthreads();
    if (t == 0) {
        float mm = sred[0];
#pragma unroll
        for (int w = 1; w < 8; w++) mm = fmaxf(mm, sred[w]);
        sbcast = mm;
    }
    __syncthreads();
    m = sbcast;

    float e0 = __expf(v0 - m), e1 = __expf(v1 - m), e2 = __expf(v2 - m);
    float ssum = e0 + e1 + e2;
#pragma unroll
    for (int o = 16; o; o >>= 1) ssum += __shfl_xor_sync(0xffffffffu, ssum, o);
    if ((t & 31) == 0) sred[t >> 5] = ssum;
    __syncthreads();
    if (t == 0) {
        float tt = sred[0];
#pragma unroll
        for (int w = 1; w < 8; w++) tt += sred[w];
        sbcast = 1.0f / tt;
    }
    __syncthreads();
    const float inv = sbcast;
    s[t]       = to_tf32(e0 * inv);
    s[t + 256] = to_tf32(e1 * inv);
    s[t + 512] = to_tf32(e2 * inv);
}

// ---------------------------------------------------------------------------
// AV GEMM: C[128,64] = P[128,768] @ Vt[64,768]^T per (qt,bh).
// BK=64, 2-stage cp.async, stride-68 smem. Writes g_O2 merged, tf32-rounded.
// 8 warps 4m x 2n, warp tile 32x32.
// ---------------------------------------------------------------------------
__global__ __launch_bounds__(256)
void av_mma()
{
    extern __shared__ float sm[];
    constexpr int ASZ = 128 * 68, BSZ = 64 * 68, STG = ASZ + BSZ;
    const uint32_t smb = smem_u32(sm);

    const int tid = threadIdx.x, lane = tid & 31, wid = tid >> 5;
    const int g4 = lane >> 2, cq = lane & 3;
    const int wm = (wid & 3) * 32, wn = (wid >> 2) * 32;
    const int qt = blockIdx.x, bh = blockIdx.y;

    const float* P = g_S  + ((size_t)bh * 768 + qt * 128) * 768;
    const float* V = g_Vt + (size_t)bh * 64 * 768;

    auto load = [&](int t, int s) {
        const uint32_t base = smb + (uint32_t)s * STG * 4;
        const int k0 = t * 64;
#pragma unroll
        for (int i = 0; i < 8; ++i) {
            int idx = tid + i * 256;
            int r = idx >> 4, seg = idx & 15;
            CP_A16(base + (uint32_t)(r * 68 + seg * 4) * 4,
                   P + (size_t)r * 768 + k0 + seg * 4);
        }
#pragma unroll
        for (int i = 0; i < 4; ++i) {
            int idx = tid + i * 256;
            int r = idx >> 4, seg = idx & 15;
            CP_A16(base + (uint32_t)(ASZ + r * 68 + seg * 4) * 4,
                   V + (size_t)r * 768 + k0 + seg * 4);
        }
    };

    float acc[2][4][4] = {};

    load(0, 0); CP_COMMIT();
    load(1, 1); CP_COMMIT();
    CP_WAIT1();
    __syncthreads();

#pragma unroll 1
    for (int t = 0; t < 12; ++t) {
        const float* As = sm + (t & 1) * STG;
        const float* Bs = As + ASZ;
#pragma unroll
        for (int ks = 0; ks < 8; ++ks) {
            uint32_t afr[2][4], bfr[4][2];
#pragma unroll
            for (int mt = 0; mt < 2; ++mt) {
                const float* p = As + (wm + mt * 16 + g4) * 68 + ks * 8 + cq;
                afr[mt][0] = __float_as_uint(p[0]);
                afr[mt][1] = __float_as_uint(p[8 * 68]);
                afr[mt][2] = __float_as_uint(p[4]);
                afr[mt][3] = __float_as_uint(p[8 * 68 + 4]);
            }
#pragma unroll
            for (int nt = 0; nt < 4; ++nt) {
                const float* p = Bs + (wn + nt * 8 + g4) * 68 + ks * 8 + cq;
                bfr[nt][0] = __float_as_uint(p[0]);
                bfr[nt][1] = __float_as_uint(p[4]);
            }
#pragma unroll
            for (int mt = 0; mt < 2; ++mt)
#pragma unroll
                for (int nt = 0; nt < 4; ++nt)
                    mma_tf32(acc[mt][nt], afr[mt], bfr[nt]);
        }
        __syncthreads();
        if (t + 2 < 12) { load(t + 2, t & 1); CP_COMMIT(); }
        if (t + 1 < 12) {
            if (t + 2 < 12) { CP_WAIT1(); } else { CP_WAIT0(); }
            __syncthreads();
        }
    }

    const int b = bh >> 4, h = bh & 15;
#pragma unroll
    for (int mt = 0; mt < 2; ++mt)
#pragma unroll
        for (int h2 = 0; h2 < 2; ++h2) {
            const int row = wm + mt * 16 + g4 + h2 * 8;
#pragma unroll
            for (int nt = 0; nt < 4; ++nt) {
                const int col = wn + nt * 8 + 2 * cq;
                *(float2*)&g_O2[((size_t)(b * 768) + qt * 128 + row) * 1024
                                + h * 64 + col] =
                    make_float2(to_tf32(acc[mt][nt][h2 * 2 + 0]),
                                to_tf32(acc[mt][nt][h2 * 2 + 1]));
            }
        }
}

// ---------------------------------------------------------------------------
extern "C" void kernel_launch(void* const* d_in, const int* in_sizes, int n_in,
                              void* d_out, int out_size)
{
    const float* query = (const float*)d_in[0];
    const float* key   = (const float*)d_in[1];
    const float* value = (const float*)d_in[2];
    const float* w_q   = (const float*)d_in[3];
    const float* b_q   = (const float*)d_in[4];
    const float* w_k   = (const float*)d_in[5];
    const float* b_k   = (const float*)d_in[6];
    const float* w_v   = (const float*)d_in[7];
    const float* b_v   = (const float*)d_in[8];
    const float* w_o   = (const float*)d_in[9];
    const float* b_o   = (const float*)d_in[10];
    const float* relE  = (const float*)d_in[11];
    float* out = (float*)d_out;

    float *xr, *wq, *wk, *wv, *wo, *qp, *kp, *o2, *ec;
    cudaGetSymbolAddress((void**)&xr, g_Xr);
    cudaGetSymbolAddress((void**)&wq, g_Wq);
    cudaGetSymbolAddress((void**)&wk, g_Wk);
    cudaGetSymbolAddress((void**)&wv, g_Wv);
    cudaGetSymbolAddress((void**)&wo, g_Wo);
    cudaGetSymbolAddress((void**)&qp, g_Qp);
    cudaGetSymbolAddress((void**)&kp, g_Kp);
    cudaGetSymbolAddress((void**)&o2, g_O2);
    cudaGetSymbolAddress((void**)&ec, g_Ec);

    const int SMEMP   = 3 * 2 * 128 * 36 * 4;            // 110592
    const int SC_SMEM = 3 * 128 * 68 * 4;                // 104448
    const int AV_SMEM = 2 * (128 * 68 + 64 * 68) * 4;    // 104448
    cudaFuncSetAttribute(proj_mma<0>, cudaFuncAttributeMaxDynamicSharedMemorySize, SMEMP);
    cudaFuncSetAttribute(proj_mma<1>, cudaFuncAttributeMaxDynamicSharedMemorySize, SMEMP);
    cudaFuncSetAttribute(proj_mma<2>, cudaFuncAttributeMaxDynamicSharedMemorySize, SMEMP);
    cudaFuncSetAttribute(scores_kernel, cudaFuncAttributeMaxDynamicSharedMemorySize, SC_SMEM);
    cudaFuncSetAttribute(av_mma,        cudaFuncAttributeMaxDynamicSharedMemorySize, AV_SMEM);

    const int NW4 = 1024 * 1024 / 4;     // weight float4 count
    const int NX4 = M_ * D_ / 4;         // X float4 count
    conv_tf32<<<(NW4 + 255) / 256, 256>>>((const float4*)w_q, (float4*)wq, NW4);
    conv_tf32<<<(NW4 + 255) / 256, 256>>>((const float4*)w_k, (float4*)wk, NW4);
    conv_tf32<<<(NW4 + 255) / 256, 256>>>((const float4*)w_v, (float4*)wv, NW4);
    conv_tf32<<<(NW4 + 255) / 256, 256>>>((const float4*)w_o, (float4*)wo, NW4);
    conv_tf32<<<(1535 * 64 / 4 + 255) / 256, 256>>>((const float4*)relE, (float4*)ec, 1535 * 64 / 4);

    conv_tf32<<<(NX4 + 255) / 256, 256>>>((const float4*)query, (float4*)xr, NX4);
    proj_mma<0><<<dim3(8, 48), 256, SMEMP>>>(xr, wq, b_q, qp);
    conv_tf32<<<(NX4 + 255) / 256, 256>>>((const float4*)key, (float4*)xr, NX4);
    proj_mma<0><<<dim3(8, 48), 256, SMEMP>>>(xr, wk, b_k, kp);
    conv_tf32<<<(NX4 + 255) / 256, 256>>>((const float4*)value, (float4*)xr, NX4);
    proj_mma<1><<<dim3(8, 48), 256, SMEMP>>>(xr, wv, b_v, nullptr);

    scores_kernel<<<dim3(6, 128), 256, SC_SMEM>>>();
    softmax_rel<<<BH_ * L_, 256>>>();
    av_mma<<<dim3(6, 128), 256, AV_SMEM>>>();

    proj_mma<2><<<dim3(8, 48), 256, SMEMP>>>(o2, wo, b_o, out);
}

// round 7
// speedup vs baseline: 1.7227x; 1.1300x over previous
#include <cuda_runtime.h>
#include <cstdint>

#define B_    8
#define L_    768
#define H_    16
#define DK_   64
#define D_    1024
#define BH_   128
#define M_    6144
#define SCALE 0.125f

// Scratch (device globals; allocation forbidden)
__device__ float g_Xr[M_ * D_];                        // tf32-rounded input X
__device__ float g_Wq[D_ * D_], g_Wk[D_ * D_], g_Wv[D_ * D_], g_Wo[D_ * D_];
__device__ float g_Qp[BH_ * L_ * DK_];                 // [bh][l][dk] tf32
__device__ float g_Kp[BH_ * L_ * DK_];                 // tf32
__device__ float g_Vt[BH_ * DK_ * L_];                 // V^T [bh][dk][l] tf32
__device__ float g_Ec[1535 * 64];                      // tf32 rel embedding
__device__ float g_S [(size_t)BH_ * L_ * L_];          // unnormalized probs (tf32)
__device__ float g_InvSum[BH_ * L_];                   // 1/rowsum
__device__ float g_O2[(size_t)M_ * D_];                // attn out, merged, tf32

__device__ __forceinline__ float to_tf32(float x) {
    float r;
    asm("cvt.rna.tf32.f32 %0, %1;" : "=f"(r) : "f"(x));
    return r;
}
__device__ __forceinline__ uint32_t smem_u32(const void* p) {
    uint32_t a;
    asm("{ .reg .u64 t; cvta.to.shared.u64 t, %1; cvt.u32.u64 %0, t; }"
        : "=r"(a) : "l"(p));
    return a;
}
__device__ __forceinline__ void mma_tf32(float* d, const uint32_t* a, const uint32_t* b) {
    asm volatile(
        "mma.sync.aligned.m16n8k8.row.col.f32.tf32.tf32.f32 "
        "{%0,%1,%2,%3}, {%4,%5,%6,%7}, {%8,%9}, {%0,%1,%2,%3};"
        : "+f"(d[0]), "+f"(d[1]), "+f"(d[2]), "+f"(d[3])
        : "r"(a[0]), "r"(a[1]), "r"(a[2]), "r"(a[3]), "r"(b[0]), "r"(b[1]));
}
#define CP_A16(dst, src) \
    asm volatile("cp.async.ca.shared.global [%0], [%1], 16;" :: "r"(dst), "l"(src) : "memory")
#define CP_A16Z(dst, src, sz) \
    asm volatile("cp.async.ca.shared.global [%0], [%1], 16, %2;" :: "r"(dst), "l"(src), "r"(sz) : "memory")
#define CP_COMMIT() asm volatile("cp.async.commit_group;" ::: "memory")
#define CP_WAIT2()  asm volatile("cp.async.wait_group 2;" ::: "memory")
#define CP_WAIT1()  asm volatile("cp.async.wait_group 1;" ::: "memory")
#define CP_WAIT0()  asm volatile("cp.async.wait_group 0;" ::: "memory")

// ---------------------------------------------------------------------------
// tf32 pre-round
// ---------------------------------------------------------------------------
__global__ __launch_bounds__(256)
void conv_tf32(const float4* __restrict__ in, float4* __restrict__ out, int n4)
{
    int i = blockIdx.x * 256 + threadIdx.x;
    if (i < n4) {
        float4 v = in[i];
        out[i] = make_float4(to_tf32(v.x), to_tf32(v.y), to_tf32(v.z), to_tf32(v.w));
    }
}

// ---------------------------------------------------------------------------
// Projection GEMM (R6-proven): BK=32, 3-stage cp.async, stride-36 smem.
// MODE 0: Q/K proj (head-split, tf32)  MODE 1: V proj (g_Vt^T, tf32)
// MODE 2: out proj (plain fp32)
// ---------------------------------------------------------------------------
template<int MODE>
__global__ __launch_bounds__(256)
void proj_mma(const float* __restrict__ Ag, const float* __restrict__ Bg,
              const float* __restrict__ bias, float* __restrict__ OUT)
{
    extern __shared__ float sm[];
    const uint32_t smb = smem_u32(sm);
    constexpr int STG = 2 * 128 * 36;

    const int tid = threadIdx.x, lane = tid & 31, wid = tid >> 5;
    const int g4 = lane >> 2, cq = lane & 3;
    const int wm = (wid & 1) * 64, wn = (wid >> 1) * 32;

    const float* Arow = Ag + (size_t)(blockIdx.y * 128) * 1024;
    const float* Brow = Bg + (size_t)(blockIdx.x * 128) * 1024;

    auto loadAB = [&](int t, int s) {
        const uint32_t base = smb + (uint32_t)s * STG * 4;
        const int k0 = t * 32;
#pragma unroll
        for (int i = 0; i < 4; ++i) {
            int idx = tid + i * 256;
            int r = idx >> 3, seg = idx & 7;
            CP_A16(base + (uint32_t)(r * 36 + seg * 4) * 4,
                   Arow + (size_t)r * 1024 + k0 + seg * 4);
        }
#pragma unroll
        for (int i = 0; i < 4; ++i) {
            int idx = tid + i * 256;
            int r = idx >> 3, seg = idx & 7;
            CP_A16(base + (uint32_t)(128 * 36 + r * 36 + seg * 4) * 4,
                   Brow + (size_t)r * 1024 + k0 + seg * 4);
        }
    };

    float acc[4][4][4] = {};

    loadAB(0, 0); CP_COMMIT();
    loadAB(1, 1); CP_COMMIT();

    for (int t = 0; t < 32; ++t) {
        if (t < 31) { CP_WAIT1(); } else { CP_WAIT0(); }
        __syncthreads();
        if (t + 2 < 32) { loadAB(t + 2, (t + 2) % 3); CP_COMMIT(); }

        const float* As = sm + (t % 3) * STG;
        const float* Bs = As + 128 * 36;
#pragma unroll
        for (int ks = 0; ks < 4; ++ks) {
            uint32_t afr[4][4], bfr[4][2];
#pragma unroll
            for (int m = 0; m < 4; ++m) {
                const float* p = As + (wm + m * 16 + g4) * 36 + ks * 8 + cq;
                afr[m][0] = __float_as_uint(p[0]);
                afr[m][1] = __float_as_uint(p[8 * 36]);
                afr[m][2] = __float_as_uint(p[4]);
                afr[m][3] = __float_as_uint(p[8 * 36 + 4]);
            }
#pragma unroll
            for (int n = 0; n < 4; ++n) {
                const float* p = Bs + (wn + n * 8 + g4) * 36 + ks * 8 + cq;
                bfr[n][0] = __float_as_uint(p[0]);
                bfr[n][1] = __float_as_uint(p[4]);
            }
#pragma unroll
            for (int m = 0; m < 4; ++m)
#pragma unroll
                for (int n = 0; n < 4; ++n)
                    mma_tf32(acc[m][n], afr[m], bfr[n]);
        }
    }

#pragma unroll
    for (int m = 0; m < 4; ++m) {
#pragma unroll
        for (int n = 0; n < 4; ++n) {
            const int col = wn + n * 8 + cq * 2;
#pragma unroll
            for (int h2 = 0; h2 < 2; ++h2) {
                const int row = wm + m * 16 + g4 + h2 * 8;
                const float c0 = acc[m][n][h2 * 2 + 0];
                const float c1 = acc[m][n][h2 * 2 + 1];
                const int mg = blockIdx.y * 128 + row;
                const int ng = blockIdx.x * 128 + col;
                if constexpr (MODE == 0) {
                    const int bb = mg / 768, l = mg - bb * 768;
                    const int hh = ng >> 6, dd = ng & 63;
                    float* dst = OUT + (((size_t)(bb * 16 + hh) * 768) + l) * 64 + dd;
                    dst[0] = to_tf32(c0 + bias[ng]);
                    dst[1] = to_tf32(c1 + bias[ng + 1]);
                } else if constexpr (MODE == 1) {
                    const int bb = mg / 768, l = mg - bb * 768;
                    const int hh = ng >> 6, dd = ng & 63;
                    g_Vt[((size_t)(bb * 16 + hh) * 64 + dd    ) * 768 + l] = to_tf32(c0 + bias[ng]);
                    g_Vt[((size_t)(bb * 16 + hh) * 64 + dd + 1) * 768 + l] = to_tf32(c1 + bias[ng + 1]);
                } else {
                    float* dst = OUT + (size_t)mg * 1024 + ng;
                    dst[0] = c0 + bias[ng];
                    dst[1] = c1 + bias[ng + 1];
                }
            }
        }
    }
}

// ---------------------------------------------------------------------------
// Fused scores + rel + exp + rowsum. One CTA per (qt, bh).
// Tile stream: w0, w1, c0, w2, c1, w3, c2, w4, c3, w5, c4, w6, c5.
// Window score tiles live in smem (2 x 128x132); content epilogue computes
// p = exp(SCALE*(s + rel)) and accumulates row sums; writes p to g_S,
// 1/rowsum to g_InvSum. 8 warps: 4m x 2n, warp tile 32x64.
// ---------------------------------------------------------------------------
__global__ __launch_bounds__(256)
void scores_fused()
{
    extern __shared__ float sm[];
    float* Bbuf = sm;                       // [2][128*68]
    float* Wbuf = sm + 2 * 128 * 68;        // [2][128*132]
    const uint32_t bb_a = smem_u32(Bbuf);
    const uint32_t wq_a = smem_u32(Wbuf);   // Q staged here temporarily
    __shared__ float ssum[128];

    const int tid  = threadIdx.x;
    const int lane = tid & 31, wid = tid >> 5;
    const int g4 = lane >> 2, cq = lane & 3;
    const int wm = (wid & 3) * 32, wn = (wid >> 2) * 64;
    const int qt = blockIdx.x, bh = blockIdx.y;

    if (tid < 128) ssum[tid] = 0.f;

    const float* Qg = g_Qp + ((size_t)bh * 768 + qt * 128) * 64;
    const float* Kg = g_Kp + (size_t)bh * 768 * 64;
    const int base0 = 640 - qt * 128;

    // stage Q into Wbuf region (dead after frag extraction)
#pragma unroll
    for (int i = 0; i < 8; ++i) {
        int idx = tid + i * 256;
        int r = idx >> 4, seg = idx & 15;
        CP_A16(wq_a + (uint32_t)(r * 68 + seg * 4) * 4, Qg + r * 64 + seg * 4);
    }
    CP_COMMIT();

    auto loadB = [&](int i) {
        const uint32_t base = bb_a + (uint32_t)(i & 1) * (128 * 68 * 4);
        const bool content = (i >= 2) && ((i & 1) == 0);
        if (content) {
            const int xt = (i - 2) >> 1;
            const float* s0 = Kg + (size_t)xt * 128 * 64;
#pragma unroll
            for (int k = 0; k < 8; ++k) {
                int idx = tid + k * 256;
                int r = idx >> 4, seg = idx & 15;
                CP_A16(base + (uint32_t)(r * 68 + seg * 4) * 4, s0 + r * 64 + seg * 4);
            }
        } else {
            const int w = (i < 2) ? i : ((i + 1) >> 1);
            const int jb = base0 + w * 128;
#pragma unroll
            for (int k = 0; k < 8; ++k) {
                int idx = tid + k * 256;
                int r = idx >> 4, seg = idx & 15;
                int j = jb + r;
                int jc = (j > 1534) ? 1534 : j;
                unsigned sz = (j <= 1534) ? 16u : 0u;
                CP_A16Z(base + (uint32_t)(r * 68 + seg * 4) * 4,
                        g_Ec + (size_t)jc * 64 + seg * 4, sz);
            }
        }
    };

    loadB(0); CP_COMMIT();
    loadB(1); CP_COMMIT();

    CP_WAIT2();          // Q ready
    __syncthreads();

    // persistent Q A-fragments
    uint32_t afr[8][2][4];
#pragma unroll
    for (int ks = 0; ks < 8; ++ks)
#pragma unroll
        for (int mt = 0; mt < 2; ++mt) {
            const float* q = Wbuf + (wm + mt * 16 + g4) * 68 + ks * 8 + cq;
            afr[ks][mt][0] = __float_as_uint(q[0]);
            afr[ks][mt][1] = __float_as_uint(q[8 * 68]);
            afr[ks][mt][2] = __float_as_uint(q[4]);
            afr[ks][mt][3] = __float_as_uint(q[8 * 68 + 4]);
        }
    __syncthreads();     // all frags extracted before Wbuf is overwritten

    CP_WAIT1();          // tile 0 ready
    __syncthreads();

    float rsum[4] = {0.f, 0.f, 0.f, 0.f};

#pragma unroll 1
    for (int i = 0; i < 13; ++i) {
        const float* Bsb = Bbuf + (i & 1) * (128 * 68);
        float acc[2][8][4] = {};

#pragma unroll
        for (int ks = 0; ks < 8; ++ks) {
            uint32_t bfr[8][2];
#pragma unroll
            for (int nt = 0; nt < 8; ++nt) {
                const float* b = Bsb + (wn + nt * 8 + g4) * 68 + ks * 8 + cq;
                bfr[nt][0] = __float_as_uint(b[0]);
                bfr[nt][1] = __float_as_uint(b[4]);
            }
#pragma unroll
            for (int mt = 0; mt < 2; ++mt)
#pragma unroll
                for (int nt = 0; nt < 8; ++nt)
                    mma_tf32(acc[mt][nt], afr[ks][mt], bfr[nt]);
        }

        const bool content = (i >= 2) && ((i & 1) == 0);
        if (!content) {
            // window tile -> smem
            const int w = (i < 2) ? i : ((i + 1) >> 1);
            float* Wd = Wbuf + (w & 1) * (128 * 132);
#pragma unroll
            for (int mt = 0; mt < 2; ++mt)
#pragma unroll
                for (int h2 = 0; h2 < 2; ++h2) {
                    const int row = wm + mt * 16 + g4 + h2 * 8;
#pragma unroll
                    for (int nt = 0; nt < 8; ++nt) {
                        const int col = wn + nt * 8 + 2 * cq;
                        Wd[row * 132 + col    ] = acc[mt][nt][h2 * 2 + 0];
                        Wd[row * 132 + col + 1] = acc[mt][nt][h2 * 2 + 1];
                    }
                }
        } else {
            // content tile: add rel from smem windows, exp, rowsum, store p
            const int xt = (i - 2) >> 1;
            const float* W0 = Wbuf + (xt & 1) * (128 * 132);
            const float* W1 = Wbuf + ((xt + 1) & 1) * (128 * 132);
            float* Sd = g_S + ((size_t)bh * 768 + qt * 128) * 768 + xt * 128;
#pragma unroll
            for (int mt = 0; mt < 2; ++mt)
#pragma unroll
                for (int h2 = 0; h2 < 2; ++h2) {
                    const int row = wm + mt * 16 + g4 + h2 * 8;
                    float rs = 0.f;
#pragma unroll
                    for (int nt = 0; nt < 8; ++nt) {
                        const int col = wn + nt * 8 + 2 * cq;
                        const int c0 = col - row + 127;
                        const int c1 = c0 + 1;
                        const float r0 = (c0 < 128) ? W0[row * 132 + c0]
                                                    : W1[row * 132 + c0 - 128];
                        const float r1 = (c1 < 128) ? W0[row * 132 + c1]
                                                    : W1[row * 132 + c1 - 128];
                        const float p0 = __expf(SCALE * (acc[mt][nt][h2 * 2 + 0] + r0));
                        const float p1 = __expf(SCALE * (acc[mt][nt][h2 * 2 + 1] + r1));
                        rs += p0 + p1;
                        *(float2*)&Sd[(size_t)row * 768 + col] =
                            make_float2(to_tf32(p0), to_tf32(p1));
                    }
                    rsum[mt * 2 + h2] += rs;
                }
        }

        __syncthreads();
        if (i + 2 < 13) { loadB(i + 2); CP_COMMIT(); }
        if (i + 1 < 13) {
            if (i + 2 < 13) { CP_WAIT1(); } else { CP_WAIT0(); }
            __syncthreads();
        }
    }

    // reduce row sums: over cq lanes, then across the 2 n-warps via smem
#pragma unroll
    for (int k = 0; k < 4; ++k) {
        rsum[k] += __shfl_xor_sync(0xffffffffu, rsum[k], 1);
        rsum[k] += __shfl_xor_sync(0xffffffffu, rsum[k], 2);
    }
    __syncthreads();
    if (cq == 0) {
#pragma unroll
        for (int k = 0; k < 4; ++k) {
            const int row = wm + (k >> 1) * 16 + g4 + (k & 1) * 8;
            atomicAdd(&ssum[row], rsum[k]);
        }
    }
    __syncthreads();
    if (tid < 128)
        g_InvSum[bh * 768 + qt * 128 + tid] = 1.0f / ssum[tid];
}

// ---------------------------------------------------------------------------
// AV GEMM: C[128,64] = P[128,768] @ Vt[64,768]^T per (qt,bh); normalizes by
// g_InvSum in the epilogue. BK=64, 2-stage cp.async.
// ---------------------------------------------------------------------------
__global__ __launch_bounds__(256)
void av_mma()
{
    extern __shared__ float sm[];
    constexpr int ASZ = 128 * 68, BSZ = 64 * 68, STG = ASZ + BSZ;
    const uint32_t smb = smem_u32(sm);

    const int tid = threadIdx.x, lane = tid & 31, wid = tid >> 5;
    const int g4 = lane >> 2, cq = lane & 3;
    const int wm = (wid & 3) * 32, wn = (wid >> 2) * 32;
    const int qt = blockIdx.x, bh = blockIdx.y;

    const float* P = g_S  + ((size_t)bh * 768 + qt * 128) * 768;
    const float* V = g_Vt + (size_t)bh * 64 * 768;

    auto load = [&](int t, int s) {
        const uint32_t base = smb + (uint32_t)s * STG * 4;
        const int k0 = t * 64;
#pragma unroll
        for (int i = 0; i < 8; ++i) {
            int idx = tid + i * 256;
            int r = idx >> 4, seg = idx & 15;
            CP_A16(base + (uint32_t)(r * 68 + seg * 4) * 4,
                   P + (size_t)r * 768 + k0 + seg * 4);
        }
#pragma unroll
        for (int i = 0; i < 4; ++i) {
            int idx = tid + i * 256;
            int r = idx >> 4, seg = idx & 15;
            CP_A16(base + (uint32_t)(ASZ + r * 68 + seg * 4) * 4,
                   V + (size_t)r * 768 + k0 + seg * 4);
        }
    };

    float acc[2][4][4] = {};

    load(0, 0); CP_COMMIT();
    load(1, 1); CP_COMMIT();
    CP_WAIT1();
    __syncthreads();

#pragma unroll 1
    for (int t = 0; t < 12; ++t) {
        const float* As = sm + (t & 1) * STG;
        const float* Bs = As + ASZ;
#pragma unroll
        for (int ks = 0; ks < 8; ++ks) {
            uint32_t afr[2][4], bfr[4][2];
#pragma unroll
            for (int mt = 0; mt < 2; ++mt) {
                const float* p = As + (wm + mt * 16 + g4) * 68 + ks * 8 + cq;
                afr[mt][0] = __float_as_uint(p[0]);
                afr[mt][1] = __float_as_uint(p[8 * 68]);
                afr[mt][2] = __float_as_uint(p[4]);
                afr[mt][3] = __float_as_uint(p[8 * 68 + 4]);
            }
#pragma unroll
            for (int nt = 0; nt < 4; ++nt) {
                const float* p = Bs + (wn + nt * 8 + g4) * 68 + ks * 8 + cq;
                bfr[nt][0] = __float_as_uint(p[0]);
                bfr[nt][1] = __float_as_uint(p[4]);
            }
#pragma unroll
            for (int mt = 0; mt < 2; ++mt)
#pragma unroll
                for (int nt = 0; nt < 4; ++nt)
                    mma_tf32(acc[mt][nt], afr[mt], bfr[nt]);
        }
        __syncthreads();
        if (t + 2 < 12) { load(t + 2, t & 1); CP_COMMIT(); }
        if (t + 1 < 12) {
            if (t + 2 < 12) { CP_WAIT1(); } else { CP_WAIT0(); }
            __syncthreads();
        }
    }

    const int b = bh >> 4, h = bh & 15;
#pragma unroll
    for (int mt = 0; mt < 2; ++mt)
#pragma unroll
        for (int h2 = 0; h2 < 2; ++h2) {
            const int row = wm + mt * 16 + g4 + h2 * 8;
            const float inv = g_InvSum[bh * 768 + qt * 128 + row];
#pragma unroll
            for (int nt = 0; nt < 4; ++nt) {
                const int col = wn + nt * 8 + 2 * cq;
                *(float2*)&g_O2[((size_t)(b * 768) + qt * 128 + row) * 1024
                                + h * 64 + col] =
                    make_float2(to_tf32(acc[mt][nt][h2 * 2 + 0] * inv),
                                to_tf32(acc[mt][nt][h2 * 2 + 1] * inv));
            }
        }
}

// ---------------------------------------------------------------------------
extern "C" void kernel_launch(void* const* d_in, const int* in_sizes, int n_in,
                              void* d_out, int out_size)
{
    const float* query = (const float*)d_in[0];
    const float* key   = (const float*)d_in[1];
    const float* value = (const float*)d_in[2];
    const float* w_q   = (const float*)d_in[3];
    const float* b_q   = (const float*)d_in[4];
    const float* w_k   = (const float*)d_in[5];
    const float* b_k   = (const float*)d_in[6];
    const float* w_v   = (const float*)d_in[7];
    const float* b_v   = (const float*)d_in[8];
    const float* w_o   = (const float*)d_in[9];
    const float* b_o   = (const float*)d_in[10];
    const float* relE  = (const float*)d_in[11];
    float* out = (float*)d_out;

    float *xr, *wq, *wk, *wv, *wo, *qp, *kp, *o2, *ec;
    cudaGetSymbolAddress((void**)&xr, g_Xr);
    cudaGetSymbolAddress((void**)&wq, g_Wq);
    cudaGetSymbolAddress((void**)&wk, g_Wk);
    cudaGetSymbolAddress((void**)&wv, g_Wv);
    cudaGetSymbolAddress((void**)&wo, g_Wo);
    cudaGetSymbolAddress((void**)&qp, g_Qp);
    cudaGetSymbolAddress((void**)&kp, g_Kp);
    cudaGetSymbolAddress((void**)&o2, g_O2);
    cudaGetSymbolAddress((void**)&ec, g_Ec);

    const int SMEMP   = 3 * 2 * 128 * 36 * 4;                    // 110592
    const int SC_SMEM = (2 * 128 * 68 + 2 * 128 * 132) * 4;      // 204800
    const int AV_SMEM = 2 * (128 * 68 + 64 * 68) * 4;            // 104448
    cudaFuncSetAttribute(proj_mma<0>, cudaFuncAttributeMaxDynamicSharedMemorySize, SMEMP);
    cudaFuncSetAttribute(proj_mma<1>, cudaFuncAttributeMaxDynamicSharedMemorySize, SMEMP);
    cudaFuncSetAttribute(proj_mma<2>, cudaFuncAttributeMaxDynamicSharedMemorySize, SMEMP);
    cudaFuncSetAttribute(scores_fused, cudaFuncAttributeMaxDynamicSharedMemorySize, SC_SMEM);
    cudaFuncSetAttribute(av_mma,       cudaFuncAttributeMaxDynamicSharedMemorySize, AV_SMEM);

    const int NW4 = 1024 * 1024 / 4;
    const int NX4 = M_ * D_ / 4;
    conv_tf32<<<(NW4 + 255) / 256, 256>>>((const float4*)w_q, (float4*)wq, NW4);
    conv_tf32<<<(NW4 + 255) / 256, 256>>>((const float4*)w_k, (float4*)wk, NW4);
    conv_tf32<<<(NW4 + 255) / 256, 256>>>((const float4*)w_v, (float4*)wv, NW4);
    conv_tf32<<<(NW4 + 255) / 256, 256>>>((const float4*)w_o, (float4*)wo, NW4);
    conv_tf32<<<(1535 * 64 / 4 + 255) / 256, 256>>>((const float4*)relE, (float4*)ec, 1535 * 64 / 4);

    conv_tf32<<<(NX4 + 255) / 256, 256>>>((const float4*)query, (float4*)xr, NX4);
    proj_mma<0><<<dim3(8, 48), 256, SMEMP>>>(xr, wq, b_q, qp);
    conv_tf32<<<(NX4 + 255) / 256, 256>>>((const float4*)key, (float4*)xr, NX4);
    proj_mma<0><<<dim3(8, 48), 256, SMEMP>>>(xr, wk, b_k, kp);
    conv_tf32<<<(NX4 + 255) / 256, 256>>>((const float4*)value, (float4*)xr, NX4);
    proj_mma<1><<<dim3(8, 48), 256, SMEMP>>>(xr, wv, b_v, nullptr);

    scores_fused<<<dim3(6, 128), 256, SC_SMEM>>>();
    av_mma<<<dim3(6, 128), 256, AV_SMEM>>>();

    proj_mma<2><<<dim3(8, 48), 256, SMEMP>>>(o2, wo, b_o, out);
}